// round 1
// baseline (speedup 1.0000x reference)
#include <cuda_runtime.h>
#include <cstdint>

// ---------------------------------------------------------------------------
// Monotone float <-> sortable signed-int encoding (involution) for atomicMax.
// ---------------------------------------------------------------------------
__device__ __forceinline__ int encf(float f) {
    int i = __float_as_int(f);
    return i ^ ((i >> 31) & 0x7fffffff);
}
__device__ __forceinline__ float decf(int e) {
    int i = e ^ ((e >> 31) & 0x7fffffff);
    return __int_as_float(i);
}

// Per-(b,ch) floor for the local branch: max(0, max_q s_q * rowmin_q).
__device__ int g_floor[64];

// ---------------------------------------------------------------------------
// Init: poison output with enc(-inf), floors with enc(0).
// ---------------------------------------------------------------------------
__global__ void init_kernel(int* __restrict__ out, int n) {
    int i = blockIdx.x * blockDim.x + threadIdx.x;
    const float NINF = __int_as_float(0xff800000);
    if (i < n) out[i] = encf(NINF);
    if (i < 64) g_floor[i] = encf(0.0f);
}

// ---------------------------------------------------------------------------
// Global branch: out[b,ch,p] = max_q sim[b,q,p] * seg[b,ch,q], ch in {0,1}.
// Grid: (QS, B). Block: HW/8 threads; each thread owns 8 columns
// (two float4 groups: [tid*4, +4) and [HW/2 + tid*4, +4)).
// Each block reduces over a q-chunk, then atomically merges (encoded ints).
// ---------------------------------------------------------------------------
__global__ void gkernel(const float* __restrict__ sim,
                        const float* __restrict__ seg,
                        int* __restrict__ out,
                        int HW, int chunk)
{
    __shared__ float2 sw[64];
    const int b   = blockIdx.y;
    const int q0  = blockIdx.x * chunk;
    const int tid = threadIdx.x;

    // preload this chunk's (w0, w1) pairs
    for (int i = tid; i < chunk; i += blockDim.x) {
        float w0 = seg[(size_t)b * 2 * HW + q0 + i];
        float w1 = seg[(size_t)b * 2 * HW + HW + q0 + i];
        sw[i] = make_float2(w0, w1);
    }
    __syncthreads();

    const float NINF = __int_as_float(0xff800000);
    const int half = HW >> 1;
    const int c0 = tid * 4;
    const int c1 = half + tid * 4;
    const float* base = sim + ((size_t)b * HW + q0) * (size_t)HW;

    float4 A0 = make_float4(NINF, NINF, NINF, NINF);  // ch0, group0
    float4 A1 = A0;                                   // ch0, group1
    float4 B0 = A0;                                   // ch1, group0
    float4 B1 = A0;                                   // ch1, group1

#pragma unroll 4
    for (int q = 0; q < chunk; ++q) {
        const float2 w = sw[q];
        const float* r = base + (size_t)q * HW;
        const float4 x = *reinterpret_cast<const float4*>(r + c0);
        const float4 y = *reinterpret_cast<const float4*>(r + c1);
        A0.x = fmaxf(A0.x, x.x * w.x);  B0.x = fmaxf(B0.x, x.x * w.y);
        A0.y = fmaxf(A0.y, x.y * w.x);  B0.y = fmaxf(B0.y, x.y * w.y);
        A0.z = fmaxf(A0.z, x.z * w.x);  B0.z = fmaxf(B0.z, x.z * w.y);
        A0.w = fmaxf(A0.w, x.w * w.x);  B0.w = fmaxf(B0.w, x.w * w.y);
        A1.x = fmaxf(A1.x, y.x * w.x);  B1.x = fmaxf(B1.x, y.x * w.y);
        A1.y = fmaxf(A1.y, y.y * w.x);  B1.y = fmaxf(B1.y, y.y * w.y);
        A1.z = fmaxf(A1.z, y.z * w.x);  B1.z = fmaxf(B1.z, y.z * w.y);
        A1.w = fmaxf(A1.w, y.w * w.x);  B1.w = fmaxf(B1.w, y.w * w.y);
    }

    int* o0 = out + (size_t)b * 4 * HW;  // ch 0
    int* o1 = o0 + HW;                   // ch 1
    atomicMax(o0 + c0 + 0, encf(A0.x));  atomicMax(o1 + c0 + 0, encf(B0.x));
    atomicMax(o0 + c0 + 1, encf(A0.y));  atomicMax(o1 + c0 + 1, encf(B0.y));
    atomicMax(o0 + c0 + 2, encf(A0.z));  atomicMax(o1 + c0 + 2, encf(B0.z));
    atomicMax(o0 + c0 + 3, encf(A0.w));  atomicMax(o1 + c0 + 3, encf(B0.w));
    atomicMax(o0 + c1 + 0, encf(A1.x));  atomicMax(o1 + c1 + 0, encf(B1.x));
    atomicMax(o0 + c1 + 1, encf(A1.y));  atomicMax(o1 + c1 + 1, encf(B1.y));
    atomicMax(o0 + c1 + 2, encf(A1.z));  atomicMax(o1 + c1 + 2, encf(B1.z));
    atomicMax(o0 + c1 + 3, encf(A1.w));  atomicMax(o1 + c1 + 3, encf(B1.w));
}

// ---------------------------------------------------------------------------
// Local branch: one warp per (b,q) row of prev_sim.
// Pass 1: per-lane top-4 (values) + row min; warp-merge to get 4th-largest cut.
// Pass 2: rescan row (L1-hit), scatter enc(s_ch * x) for x >= cut.
// Floor: max(0, s_ch * rowmin) — only atomically recorded if > 0 (almost never).
// ---------------------------------------------------------------------------
__device__ __forceinline__ void ins4(float x, float& t0, float& t1, float& t2, float& t3) {
    // caller guarantees interest; keep branch cheap
    if (x > t3) {
        t3 = x;
        float a;
        a = fminf(t2, t3); t2 = fmaxf(t2, t3); t3 = a;
        a = fminf(t1, t2); t1 = fmaxf(t1, t2); t2 = a;
        a = fminf(t0, t1); t0 = fmaxf(t0, t1); t1 = a;
    }
}

__global__ void lkernel(const float* __restrict__ sim,
                        const float* __restrict__ seg,
                        int* __restrict__ out,
                        int HW, int B)
{
    const float NINF = __int_as_float(0xff800000);
    const float PINF = __int_as_float(0x7f800000);
    const int warp = (blockIdx.x * blockDim.x + threadIdx.x) >> 5;
    const int lane = threadIdx.x & 31;
    const int nrows = B * HW;
    if (warp >= nrows) return;
    const int b = warp / HW;
    const int q = warp - b * HW;
    const float* row = sim + (size_t)warp * HW;

    float t0 = NINF, t1 = NINF, t2 = NINF, t3 = NINF;
    float lmin = PINF;

    for (int base = lane * 4; base + 3 < HW; base += 128) {
        const float4 x = *reinterpret_cast<const float4*>(row + base);
        lmin = fminf(lmin, fminf(fminf(x.x, x.y), fminf(x.z, x.w)));
        const float m4 = fmaxf(fmaxf(x.x, x.y), fmaxf(x.z, x.w));
        if (m4 > t3) {
            ins4(x.x, t0, t1, t2, t3);
            ins4(x.y, t0, t1, t2, t3);
            ins4(x.z, t0, t1, t2, t3);
            ins4(x.w, t0, t1, t2, t3);
        }
    }

    // warp-reduce row min
    for (int o = 16; o; o >>= 1)
        lmin = fminf(lmin, __shfl_xor_sync(0xffffffffu, lmin, o));

    // 4th largest across warp: 4 rounds of pop-the-max from per-lane sorted lists
    float cut = NINF;
#pragma unroll
    for (int k = 0; k < 4; ++k) {
        float M = t0;
        for (int o = 16; o; o >>= 1)
            M = fmaxf(M, __shfl_xor_sync(0xffffffffu, M, o));
        cut = M;
        if (t0 == M) { t0 = t1; t1 = t2; t2 = t3; t3 = NINF; }
    }

    const float s0 = seg[(size_t)b * 2 * HW + q];
    const float s1 = seg[(size_t)b * 2 * HW + HW + q];

    int* o2 = out + (size_t)b * 4 * HW + 2 * HW;  // ch 2 (bg local)
    int* o3 = o2 + HW;                            // ch 3 (fg local)

    // Pass 2: exact scatter of all elements >= cut (handles ties correctly)
    for (int base = lane * 4; base + 3 < HW; base += 128) {
        const float4 x = *reinterpret_cast<const float4*>(row + base);
        const float m4 = fmaxf(fmaxf(x.x, x.y), fmaxf(x.z, x.w));
        if (m4 >= cut) {
            if (x.x >= cut) { atomicMax(o2 + base + 0, encf(s0 * x.x)); atomicMax(o3 + base + 0, encf(s1 * x.x)); }
            if (x.y >= cut) { atomicMax(o2 + base + 1, encf(s0 * x.y)); atomicMax(o3 + base + 1, encf(s1 * x.y)); }
            if (x.z >= cut) { atomicMax(o2 + base + 2, encf(s0 * x.z)); atomicMax(o3 + base + 2, encf(s1 * x.z)); }
            if (x.w >= cut) { atomicMax(o2 + base + 3, encf(s0 * x.w)); atomicMax(o3 + base + 3, encf(s1 * x.w)); }
        }
    }

    if (lane == 0) {
        const float f0 = s0 * lmin;
        const float f1 = s1 * lmin;
        if (f0 > 0.0f) atomicMax(&g_floor[b * 2 + 0], encf(f0));  // prob ~0 path
        if (f1 > 0.0f) atomicMax(&g_floor[b * 2 + 1], encf(f1));
    }
}

// ---------------------------------------------------------------------------
// Finalize: decode encoded ints to floats in place; apply floor to local chans.
// ---------------------------------------------------------------------------
__global__ void fin_kernel(int* __restrict__ out, int HW, int n) {
    int i = blockIdx.x * blockDim.x + threadIdx.x;
    if (i >= n) return;
    const int ch = (i / HW) & 3;
    const int b  = i / (4 * HW);
    float v = decf(out[i]);
    if (ch >= 2) v = fmaxf(v, decf(g_floor[b * 2 + (ch - 2)]));
    reinterpret_cast<float*>(out)[i] = v;
}

// ---------------------------------------------------------------------------
// Launcher (graph-capturable: kernels only, no sync, no alloc)
// ---------------------------------------------------------------------------
extern "C" void kernel_launch(void* const* d_in, const int* in_sizes, int n_in,
                              void* d_out, int out_size)
{
    const float* init_sim = (const float*)d_in[0];
    const float* prev_sim = (const float*)d_in[1];
    const float* init_seg = (const float*)d_in[2];
    const float* prev_seg = (const float*)d_in[3];

    const long long n0 = in_sizes[0];           // B*HW*HW
    const int n2 = in_sizes[2];                 // B*2*HW
    const int HW = (int)((2 * n0) / n2);
    const int B  = n2 / (2 * HW);
    const int nout = B * 4 * HW;

    init_kernel<<<(nout + 255) / 256, 256>>>((int*)d_out, nout);

    // q-split for the global kernel: chunk <= 64, divides HW
    int QS = (HW + 63) / 64;
    while (HW % QS) QS++;
    const int chunk = HW / QS;
    dim3 gg(QS, B);
    const int gthreads = HW / 8;  // 288 for HW=2304; each thread owns 8 columns
    gkernel<<<gg, gthreads>>>(init_sim, init_seg, (int*)d_out, HW, chunk);

    const int nrows = B * HW;
    lkernel<<<(nrows + 7) / 8, 256>>>(prev_sim, prev_seg, (int*)d_out, HW, B);

    fin_kernel<<<(nout + 255) / 256, 256>>>((int*)d_out, HW, nout);
}

// round 2
// speedup vs baseline: 1.0921x; 1.0921x over previous
#include <cuda_runtime.h>
#include <cstdint>

// ---------------------------------------------------------------------------
// Monotone float <-> sortable UNSIGNED encoding. Key property: 0 is a strict
// bottom (0 < enc(x) for all floats incl. -inf), so cudaMemsetAsync(0) is a
// valid init for atomicMax accumulation. dec(0) = NaN, resolved by fmaxf.
//   positive f: u = bits + 0x80000000 ;  negative f: u = ~bits
// ---------------------------------------------------------------------------
__device__ __forceinline__ unsigned encf(float f) {
    unsigned u = __float_as_uint(f);
    return u ^ ((unsigned)((int)u >> 31) | 0x80000000u);
}
__device__ __forceinline__ float decf(unsigned u) {
    unsigned m = (u & 0x80000000u) ? 0x80000000u : 0xffffffffu;
    return __uint_as_float(u ^ m);
}

// Per-(b,ch) floor for the local branch: max(0, max_q s_q * rowmin_q).
// Zero-initialized at module load; atomicMax with identical values each replay
// is idempotent -> deterministic. dec(0)=NaN is clamped to 0 in fin.
__device__ unsigned g_floor[64];

// ---------------------------------------------------------------------------
// Local-branch helper: branch-light sorted-4 insert (t0 >= t1 >= t2 >= t3).
// ---------------------------------------------------------------------------
__device__ __forceinline__ void ins4(float x, float& t0, float& t1, float& t2, float& t3) {
    if (x > t3) {
        t3 = x;
        float a;
        a = fminf(t2, t3); t2 = fmaxf(t2, t3); t3 = a;
        a = fminf(t1, t2); t1 = fmaxf(t1, t2); t2 = a;
        a = fminf(t0, t1); t0 = fmaxf(t0, t1); t1 = a;
    }
}

// ---------------------------------------------------------------------------
// Fused kernel. Block size 288 (9 warps).
//   blockIdx.x <  LBLK : local branch, 9 rows of prev_sim per block (1/warp)
//   blockIdx.x >= LBLK : global branch, one (b, q-chunk) tile of init_sim
// Both paths stream independent HBM regions -> overlap hides tails.
// ---------------------------------------------------------------------------
__global__ void __launch_bounds__(288) main_kernel(
    const float* __restrict__ init_sim,
    const float* __restrict__ prev_sim,
    const float* __restrict__ init_seg,
    const float* __restrict__ prev_seg,
    unsigned* __restrict__ out,
    int HW, int chunk, int QS, int LBLK, int nrows)
{
    __shared__ float2 sw[64];
    const float NINF = __int_as_float(0xff800000);

    if (blockIdx.x >= LBLK) {
        // ================= GLOBAL BRANCH =================
        const int gb  = blockIdx.x - LBLK;
        const int b   = gb / QS;
        const int q0  = (gb - b * QS) * chunk;
        const int tid = threadIdx.x;

        for (int i = tid; i < chunk; i += blockDim.x) {
            float w0 = init_seg[(size_t)b * 2 * HW + q0 + i];
            float w1 = init_seg[(size_t)b * 2 * HW + HW + q0 + i];
            sw[i] = make_float2(w0, w1);
        }
        __syncthreads();

        const int half = HW >> 1;
        const int c0 = tid * 4;
        const int c1 = half + tid * 4;
        const float* base = init_sim + ((size_t)b * HW + q0) * (size_t)HW;

        float4 A0 = make_float4(NINF, NINF, NINF, NINF);
        float4 A1 = A0, B0 = A0, B1 = A0;

#pragma unroll 4
        for (int q = 0; q < chunk; ++q) {
            const float2 w = sw[q];
            const float* r = base + (size_t)q * HW;
            const float4 x = *reinterpret_cast<const float4*>(r + c0);
            const float4 y = *reinterpret_cast<const float4*>(r + c1);
            A0.x = fmaxf(A0.x, x.x * w.x);  B0.x = fmaxf(B0.x, x.x * w.y);
            A0.y = fmaxf(A0.y, x.y * w.x);  B0.y = fmaxf(B0.y, x.y * w.y);
            A0.z = fmaxf(A0.z, x.z * w.x);  B0.z = fmaxf(B0.z, x.z * w.y);
            A0.w = fmaxf(A0.w, x.w * w.x);  B0.w = fmaxf(B0.w, x.w * w.y);
            A1.x = fmaxf(A1.x, y.x * w.x);  B1.x = fmaxf(B1.x, y.x * w.y);
            A1.y = fmaxf(A1.y, y.y * w.x);  B1.y = fmaxf(B1.y, y.y * w.y);
            A1.z = fmaxf(A1.z, y.z * w.x);  B1.z = fmaxf(B1.z, y.z * w.y);
            A1.w = fmaxf(A1.w, y.w * w.x);  B1.w = fmaxf(B1.w, y.w * w.y);
        }

        unsigned* o0 = out + (size_t)b * 4 * HW;  // ch 0
        unsigned* o1 = o0 + HW;                   // ch 1
        atomicMax(o0 + c0 + 0, encf(A0.x));  atomicMax(o1 + c0 + 0, encf(B0.x));
        atomicMax(o0 + c0 + 1, encf(A0.y));  atomicMax(o1 + c0 + 1, encf(B0.y));
        atomicMax(o0 + c0 + 2, encf(A0.z));  atomicMax(o1 + c0 + 2, encf(B0.z));
        atomicMax(o0 + c0 + 3, encf(A0.w));  atomicMax(o1 + c0 + 3, encf(B0.w));
        atomicMax(o0 + c1 + 0, encf(A1.x));  atomicMax(o1 + c1 + 0, encf(B1.x));
        atomicMax(o0 + c1 + 1, encf(A1.y));  atomicMax(o1 + c1 + 1, encf(B1.y));
        atomicMax(o0 + c1 + 2, encf(A1.z));  atomicMax(o1 + c1 + 2, encf(B1.z));
        atomicMax(o0 + c1 + 3, encf(A1.w));  atomicMax(o1 + c1 + 3, encf(B1.w));
    } else {
        // ================= LOCAL BRANCH =================
        const float PINF = __int_as_float(0x7f800000);
        const int wid  = threadIdx.x >> 5;
        const int lane = threadIdx.x & 31;
        const int rowi = blockIdx.x * 9 + wid;
        if (rowi >= nrows) return;
        const int b = rowi / HW;
        const int q = rowi - b * HW;
        const float* row = prev_sim + (size_t)rowi * HW;

        float t0 = NINF, t1 = NINF, t2 = NINF, t3 = NINF;
        float lmin = PINF;

#pragma unroll 3
        for (int base = lane * 4; base + 3 < HW; base += 128) {
            const float4 x = *reinterpret_cast<const float4*>(row + base);
            lmin = fminf(lmin, fminf(fminf(x.x, x.y), fminf(x.z, x.w)));
            const float m4 = fmaxf(fmaxf(x.x, x.y), fmaxf(x.z, x.w));
            if (m4 > t3) {
                ins4(x.x, t0, t1, t2, t3);
                ins4(x.y, t0, t1, t2, t3);
                ins4(x.z, t0, t1, t2, t3);
                ins4(x.w, t0, t1, t2, t3);
            }
        }

        // warp-reduce row min
        for (int o = 16; o; o >>= 1)
            lmin = fminf(lmin, __shfl_xor_sync(0xffffffffu, lmin, o));

        // 4th-largest across warp: 4 rounds of pop-the-max
        float cut = NINF;
#pragma unroll
        for (int k = 0; k < 4; ++k) {
            float M = t0;
            for (int o = 16; o; o >>= 1)
                M = fmaxf(M, __shfl_xor_sync(0xffffffffu, M, o));
            cut = M;
            if (t0 == M) { t0 = t1; t1 = t2; t2 = t3; t3 = NINF; }
        }

        const float s0 = prev_seg[(size_t)b * 2 * HW + q];
        const float s1 = prev_seg[(size_t)b * 2 * HW + HW + q];

        unsigned* o2 = out + (size_t)b * 4 * HW + 2 * HW;  // ch 2
        unsigned* o3 = o2 + HW;                            // ch 3

        // Pass 2: rescan row from L1, scatter kept elements (>= cut, ties incl.)
        for (int base = lane * 4; base + 3 < HW; base += 128) {
            const float4 x = *reinterpret_cast<const float4*>(row + base);
            const float m4 = fmaxf(fmaxf(x.x, x.y), fmaxf(x.z, x.w));
            if (m4 >= cut) {
                if (x.x >= cut) { atomicMax(o2 + base + 0, encf(s0 * x.x)); atomicMax(o3 + base + 0, encf(s1 * x.x)); }
                if (x.y >= cut) { atomicMax(o2 + base + 1, encf(s0 * x.y)); atomicMax(o3 + base + 1, encf(s1 * x.y)); }
                if (x.z >= cut) { atomicMax(o2 + base + 2, encf(s0 * x.z)); atomicMax(o3 + base + 2, encf(s1 * x.z)); }
                if (x.w >= cut) { atomicMax(o2 + base + 3, encf(s0 * x.w)); atomicMax(o3 + base + 3, encf(s1 * x.w)); }
            }
        }

        if (lane == 0) {
            const float f0 = s0 * lmin;
            const float f1 = s1 * lmin;
            if (f0 > 0.0f) atomicMax(&g_floor[b * 2 + 0], encf(f0));
            if (f1 > 0.0f) atomicMax(&g_floor[b * 2 + 1], encf(f1));
        }
    }
}

// ---------------------------------------------------------------------------
// Finalize: decode in place (uint4), apply floor to local channels.
// dec(0)=NaN; fmaxf(NaN, y) = y resolves untouched cells to the floor (0).
// ---------------------------------------------------------------------------
__global__ void fin_kernel(unsigned* __restrict__ out, int HW, int n4) {
    int t = blockIdx.x * blockDim.x + threadIdx.x;
    if (t >= n4) return;
    uint4 r = reinterpret_cast<uint4*>(out)[t];
    const int i  = t * 4;
    const int ch = (i / HW) & 3;
    const int b  = i / (4 * HW);

    float4 v;
    if (ch >= 2) {
        float fl = fmaxf(decf(g_floor[b * 2 + (ch - 2)]), 0.0f);  // NaN -> 0
        v.x = fmaxf(decf(r.x), fl);
        v.y = fmaxf(decf(r.y), fl);
        v.z = fmaxf(decf(r.z), fl);
        v.w = fmaxf(decf(r.w), fl);
    } else {
        v.x = decf(r.x); v.y = decf(r.y); v.z = decf(r.z); v.w = decf(r.w);
    }
    reinterpret_cast<float4*>(out)[t] = v;
}

// ---------------------------------------------------------------------------
// Launcher (graph-capturable: memset + 2 kernels, no sync, no alloc)
// ---------------------------------------------------------------------------
extern "C" void kernel_launch(void* const* d_in, const int* in_sizes, int n_in,
                              void* d_out, int out_size)
{
    const float* init_sim = (const float*)d_in[0];
    const float* prev_sim = (const float*)d_in[1];
    const float* init_seg = (const float*)d_in[2];
    const float* prev_seg = (const float*)d_in[3];

    const long long n0 = in_sizes[0];           // B*HW*HW
    const int n2 = in_sizes[2];                 // B*2*HW
    const int HW = (int)((2 * n0) / n2);
    const int B  = n2 / (2 * HW);
    const int nout = B * 4 * HW;

    cudaMemsetAsync(d_out, 0, (size_t)nout * sizeof(unsigned));

    // global-branch q-split: chunk <= 64, divides HW
    int QS = (HW + 63) / 64;
    while (HW % QS) QS++;
    const int chunk = HW / QS;

    const int nrows = B * HW;
    const int LBLK  = (nrows + 8) / 9;          // 9 rows per local block
    const int GBLK  = QS * B;

    main_kernel<<<LBLK + GBLK, 288>>>(init_sim, prev_sim, init_seg, prev_seg,
                                      (unsigned*)d_out, HW, chunk, QS, LBLK, nrows);

    const int n4 = nout / 4;
    fin_kernel<<<(n4 + 255) / 256, 256>>>((unsigned*)d_out, HW, n4);
}